// round 5
// baseline (speedup 1.0000x reference)
#include <cuda_runtime.h>
#include <cuda_bf16.h>
#include <math.h>

// ============================================================================
// ControlledSystem RHS (2-mass + controller + Karnopp friction w/ MLP mags).
//
// R4 post-mortem: vec8 halved thread count -> grid 512 -> occ 36% -> main
// kernel latency-bound at 13.7us (nothing saturated).
// R5: vec4 (1024 blocks, occ ~66%+) + smem table (4.1KB, two LDS.64 per
// element) + streaming __ldcs/__stcs. Setup unchanged (warp per node).
// ============================================================================

#define TBL 512
#define NNODES (TBL + 1)
#define VMIN (-8.0f)
#define INV_STEP 32.0f           // TBL / 16.0  (range [-8, 8])
#define STEP (1.0f / 32.0f)

__device__ __align__(8) float2 g_nodes[NNODES];  // (kinetic, stiction) post-softplus
__device__ float g_scalars[4];                   // K, p_ctrl, K*(z_ctrl - p_ctrl)

// ---------------------------------------------------------------------------

__device__ __forceinline__ float fast_tanh(float x) {
    return 1.0f - 2.0f / (__expf(2.0f * x) + 1.0f);
}

__device__ __forceinline__ float fast_softplus(float x) {
    if (x > 15.0f) return x;
    return log1pf(__expf(x));
}

// One warp per node; lane handles hidden units (lane) and (lane+32).
__global__ void setup_nodes(const float* __restrict__ logK,
                            const float* __restrict__ logz,
                            const float* __restrict__ logp,
                            const float* __restrict__ W1,
                            const float* __restrict__ b1,
                            const float* __restrict__ W2,
                            const float* __restrict__ b2) {
    int gtid = blockIdx.x * blockDim.x + threadIdx.x;
    int node = gtid >> 5;
    int lane = gtid & 31;

    if (gtid == 0) {
        float K  = expf(logK[0]);
        float zc = expf(logz[0]);
        float pc = expf(logp[0]);
        g_scalars[0] = K;
        g_scalars[1] = pc;
        g_scalars[2] = K * (zc - pc);
    }
    if (node >= NNODES) return;

    float v = VMIN + (float)node * STEP;
    float o0 = 0.0f, o1 = 0.0f;
#pragma unroll
    for (int r = 0; r < 2; ++r) {
        int j = lane + 32 * r;
        float h = fast_tanh(fmaf(v, W1[j], b1[j]));
        o0 = fmaf(h, W2[2 * j + 0], o0);
        o1 = fmaf(h, W2[2 * j + 1], o1);
    }
#pragma unroll
    for (int off = 16; off > 0; off >>= 1) {
        o0 += __shfl_down_sync(0xffffffffu, o0, off);
        o1 += __shfl_down_sync(0xffffffffu, o1, off);
    }
    if (lane == 0) {
        o0 += b2[0];
        o1 += b2[1];
        g_nodes[node] = make_float2(fast_softplus(o0), fast_softplus(o1));
    }
}

// ---------------------------------------------------------------------------
// Per-element physics. M1=1, M2=1.5, K1=2, K2=3, C1=0.5, C2=0.8, dv=0.01,
// x2_ref = 0.5*sin(0.5*t).
// dv1 = u - K1*x1 - C1*v1 - K2*(x1-x2) - C2*(v1-v2)
//     = u - 5*x1 - 1.3*v1 + 3*x2 + 0.8*v2            (flattened to FMAs)
// ---------------------------------------------------------------------------

__device__ __forceinline__ void rhs_one(float tt, float x1, float v1, float x2,
                                        float v2, float xc,
                                        float kin, float sti,
                                        float K, float pc, float Kzp,
                                        float& d0, float& d1, float& d2,
                                        float& d3, float& d4) {
    float x2r = 0.5f * __sinf(0.5f * tt);
    float e = x2r - x2;
    d4 = fmaf(-pc, xc, e);                 // d_xc
    float u = fmaf(Kzp, xc, K * e);

    d0 = v1;                               // dx1
    float acc = fmaf(-5.0f, x1, u);
    acc = fmaf(-1.3f, v1, acc);
    acc = fmaf(3.0f, x2, acc);
    d1 = fmaf(0.8f, v2, acc);              // dv1 (M1=1)
    d2 = v2;                               // dx2

    float F = fmaf(3.0f, x1 - x2, 0.8f * (v1 - v2));   // F_net

    float Ff = (fabsf(v2) < 0.01f)
                   ? (-fminf(fmaxf(F, -sti), sti))   // static: -clip(F,+/-sti)
                   : (-copysignf(kin, v2));          // kinetic
    d3 = (F + Ff) * (1.0f / 1.5f);         // dv2 (M2=1.5)
}

// table lookup from shared memory, linear interpolation
__device__ __forceinline__ void lookup(const float2* __restrict__ s_nodes,
                                       float v2, float& kin, float& sti) {
    float vcl = fminf(fmaxf(v2, -8.0f), 8.0f);
    float xi = (vcl + 8.0f) * INV_STEP;
    int idx = (int)xi;
    idx = min(idx, TBL - 1);
    float fr = xi - (float)idx;
    float2 a = s_nodes[idx];
    float2 b = s_nodes[idx + 1];
    kin = fmaf(fr, b.x - a.x, a.x);
    sti = fmaf(fr, b.y - a.y, a.y);
}

// ---------------------------------------------------------------------------
// Main streaming kernel: 4 elements per thread, smem table, front-batched
// global loads, streaming cache hints.
// ---------------------------------------------------------------------------

__global__ __launch_bounds__(256) void rhs_kernel_vec4(
    const float* __restrict__ t,
    const float* __restrict__ z,
    float* __restrict__ out, int N) {
    __shared__ __align__(8) float2 s_nodes[NNODES];
    for (int i = threadIdx.x; i < NNODES; i += blockDim.x) {
        s_nodes[i] = g_nodes[i];
    }

    float K   = g_scalars[0];
    float pc  = g_scalars[1];
    float Kzp = g_scalars[2];

    long long base = (long long)(blockIdx.x * blockDim.x + threadIdx.x) * 4;
    long long NN = N;

    // front-batch all 6 input LDG.128 while the smem fill is in flight
    float4 v2v = __ldcs((const float4*)(z + 3 * NN + base));
    float4 tv  = __ldcs((const float4*)(t + base));
    float4 x1v = __ldcs((const float4*)(z + base));
    float4 v1v = __ldcs((const float4*)(z + NN + base));
    float4 x2v = __ldcs((const float4*)(z + 2 * NN + base));
    float4 xcv = __ldcs((const float4*)(z + 4 * NN + base));

    __syncthreads();   // smem table ready

    float k0, s0, k1, s1, k2, s2, k3, s3;
    lookup(s_nodes, v2v.x, k0, s0);
    lookup(s_nodes, v2v.y, k1, s1);
    lookup(s_nodes, v2v.z, k2, s2);
    lookup(s_nodes, v2v.w, k3, s3);

    float4 o0, o1, o2, o3, o4;
    rhs_one(tv.x, x1v.x, v1v.x, x2v.x, v2v.x, xcv.x, k0, s0, K, pc, Kzp, o0.x, o1.x, o2.x, o3.x, o4.x);
    rhs_one(tv.y, x1v.y, v1v.y, x2v.y, v2v.y, xcv.y, k1, s1, K, pc, Kzp, o0.y, o1.y, o2.y, o3.y, o4.y);
    rhs_one(tv.z, x1v.z, v1v.z, x2v.z, v2v.z, xcv.z, k2, s2, K, pc, Kzp, o0.z, o1.z, o2.z, o3.z, o4.z);
    rhs_one(tv.w, x1v.w, v1v.w, x2v.w, v2v.w, xcv.w, k3, s3, K, pc, Kzp, o0.w, o1.w, o2.w, o3.w, o4.w);

    __stcs((float4*)(out + base),          o0);
    __stcs((float4*)(out + NN + base),     o1);
    __stcs((float4*)(out + 2 * NN + base), o2);
    __stcs((float4*)(out + 3 * NN + base), o3);
    __stcs((float4*)(out + 4 * NN + base), o4);
}

// scalar fallback (N % 4 != 0) -- table straight from global
__global__ void rhs_kernel_scalar(const float* __restrict__ t,
                                  const float* __restrict__ z,
                                  float* __restrict__ out, int N) {
    float K   = g_scalars[0];
    float pc  = g_scalars[1];
    float Kzp = g_scalars[2];

    long long i = blockIdx.x * blockDim.x + threadIdx.x;
    if (i >= N) return;
    long long NN = N;
    float v2 = z[3 * NN + i];

    float vcl = fminf(fmaxf(v2, -8.0f), 8.0f);
    float xi = (vcl + 8.0f) * INV_STEP;
    int idx = (int)xi;
    idx = min(idx, TBL - 1);
    float fr = xi - (float)idx;
    float2 a = g_nodes[idx];
    float2 b = g_nodes[idx + 1];
    float kin = fmaf(fr, b.x - a.x, a.x);
    float sti = fmaf(fr, b.y - a.y, a.y);

    float d0, d1, d2, d3, d4;
    rhs_one(t[i], z[i], z[NN + i], z[2 * NN + i], v2, z[4 * NN + i],
            kin, sti, K, pc, Kzp, d0, d1, d2, d3, d4);
    out[i]          = d0;
    out[NN + i]     = d1;
    out[2 * NN + i] = d2;
    out[3 * NN + i] = d3;
    out[4 * NN + i] = d4;
}

// ---------------------------------------------------------------------------

extern "C" void kernel_launch(void* const* d_in, const int* in_sizes, int n_in,
                              void* d_out, int out_size) {
    const float* t    = (const float*)d_in[0];
    const float* z    = (const float*)d_in[1];
    const float* logK = (const float*)d_in[2];
    const float* logz = (const float*)d_in[3];
    const float* logp = (const float*)d_in[4];
    const float* W1   = (const float*)d_in[5];
    const float* b1   = (const float*)d_in[6];
    const float* W2   = (const float*)d_in[7];
    const float* b2   = (const float*)d_in[8];
    float* out = (float*)d_out;
    int N = in_sizes[0];

    // one warp per node
    int setup_threads = NNODES * 32;
    setup_nodes<<<(setup_threads + 255) / 256, 256>>>(logK, logz, logp, W1, b1, W2, b2);

    if ((N & 3) == 0) {
        int nthreads = N / 4;
        rhs_kernel_vec4<<<(nthreads + 255) / 256, 256>>>(t, z, out, N);
    } else {
        rhs_kernel_scalar<<<(N + 255) / 256, 256>>>(t, z, out, N);
    }
}

// round 6
// speedup vs baseline: 1.3510x; 1.3510x over previous
#include <cuda_runtime.h>
#include <cuda_bf16.h>
#include <math.h>

// ============================================================================
// ControlledSystem RHS (2-mass + controller + Karnopp friction w/ MLP mags).
//
// R5 post-mortem: smem table staging is a measured LOSS (R1 global-__ldg
// vec4 = 11.9us vs smem vec4 = 14.7us): the fill loads + STS + barrier +
// reg pressure cost more than the gather saves. Revert main kernel to the
// R1 structure; only change = table 4096 -> 512 entries (64KB -> 8KB,
// L1-resident). Setup = fast warp-per-node version writing the packed
// float4 entries directly (no pack kernel).
// ============================================================================

#define TBL 512
#define NNODES (TBL + 1)
#define VMIN (-8.0f)
#define INV_STEP 32.0f           // TBL / 16.0  (range [-8, 8])
#define STEP (1.0f / 32.0f)

// packed table: g_table[i] = (kin_i, sti_i, kin_{i+1}, sti_{i+1})
__device__ __align__(16) float4 g_table[TBL];
__device__ float g_scalars[4];   // K, p_ctrl, K*(z_ctrl - p_ctrl)

// ---------------------------------------------------------------------------

__device__ __forceinline__ float fast_tanh(float x) {
    return 1.0f - 2.0f / (__expf(2.0f * x) + 1.0f);
}

__device__ __forceinline__ float fast_softplus(float x) {
    if (x > 15.0f) return x;
    return log1pf(__expf(x));
}

// One warp per node; lane handles hidden units (lane) and (lane+32).
// Lane 0 writes the node's (kin, sti) into BOTH packed slots that need it:
//   g_table[node].xy  and  g_table[node-1].zw
__global__ void setup_nodes(const float* __restrict__ logK,
                            const float* __restrict__ logz,
                            const float* __restrict__ logp,
                            const float* __restrict__ W1,
                            const float* __restrict__ b1,
                            const float* __restrict__ W2,
                            const float* __restrict__ b2) {
    int gtid = blockIdx.x * blockDim.x + threadIdx.x;
    int node = gtid >> 5;
    int lane = gtid & 31;

    if (gtid == 0) {
        float K  = expf(logK[0]);
        float zc = expf(logz[0]);
        float pc = expf(logp[0]);
        g_scalars[0] = K;
        g_scalars[1] = pc;
        g_scalars[2] = K * (zc - pc);
    }
    if (node >= NNODES) return;

    float v = VMIN + (float)node * STEP;
    float o0 = 0.0f, o1 = 0.0f;
#pragma unroll
    for (int r = 0; r < 2; ++r) {
        int j = lane + 32 * r;
        float h = fast_tanh(fmaf(v, W1[j], b1[j]));
        o0 = fmaf(h, W2[2 * j + 0], o0);
        o1 = fmaf(h, W2[2 * j + 1], o1);
    }
#pragma unroll
    for (int off = 16; off > 0; off >>= 1) {
        o0 += __shfl_down_sync(0xffffffffu, o0, off);
        o1 += __shfl_down_sync(0xffffffffu, o1, off);
    }
    if (lane == 0) {
        float kin = fast_softplus(o0 + b2[0]);
        float sti = fast_softplus(o1 + b2[1]);
        if (node < TBL) {
            g_table[node].x = kin;
            g_table[node].y = sti;
        }
        if (node > 0) {
            g_table[node - 1].z = kin;
            g_table[node - 1].w = sti;
        }
    }
}

// ---------------------------------------------------------------------------
// Per-element physics. M1=1, M2=1.5, K1=2, K2=3, C1=0.5, C2=0.8, dv=0.01,
// x2_ref = 0.5*sin(0.5*t).
// dv1 = u - 5*x1 - 1.3*v1 + 3*x2 + 0.8*v2   (flattened to FMAs)
// ---------------------------------------------------------------------------

__device__ __forceinline__ void rhs_one(float tt, float x1, float v1, float x2,
                                        float v2, float xc,
                                        float K, float pc, float Kzp,
                                        float& d0, float& d1, float& d2,
                                        float& d3, float& d4) {
    float x2r = 0.5f * __sinf(0.5f * tt);
    float e = x2r - x2;
    d4 = fmaf(-pc, xc, e);                 // d_xc
    float u = fmaf(Kzp, xc, K * e);

    d0 = v1;                               // dx1
    float acc = fmaf(-5.0f, x1, u);
    acc = fmaf(-1.3f, v1, acc);
    acc = fmaf(3.0f, x2, acc);
    d1 = fmaf(0.8f, v2, acc);              // dv1 (M1=1)
    d2 = v2;                               // dx2

    float F = fmaf(3.0f, x1 - x2, 0.8f * (v1 - v2));   // F_net

    // friction magnitudes via packed table (post-softplus, linear interp)
    float vcl = fminf(fmaxf(v2, -8.0f), 8.0f);
    float xi = (vcl + 8.0f) * INV_STEP;
    int idx = (int)xi;
    idx = min(idx, TBL - 1);
    float fr = xi - (float)idx;
    float4 ent = __ldg(&g_table[idx]);
    float kin = fmaf(fr, ent.z - ent.x, ent.x);
    float sti = fmaf(fr, ent.w - ent.y, ent.y);

    float Ff = (fabsf(v2) < 0.01f)
                   ? (-fminf(fmaxf(F, -sti), sti))   // static: -clip(F,+/-sti)
                   : (-copysignf(kin, v2));          // kinetic
    d3 = (F + Ff) * (1.0f / 1.5f);         // dv2 (M2=1.5)
}

// ---------------------------------------------------------------------------
// Main streaming kernel, float4 vectorized (requires N % 4 == 0) -- the R1
// structure that measured 11.9us: plain cached loads/stores, no smem.
// ---------------------------------------------------------------------------

__global__ __launch_bounds__(256) void rhs_kernel_vec(
    const float* __restrict__ t,
    const float* __restrict__ z,
    float* __restrict__ out, int N) {
    float K   = g_scalars[0];
    float pc  = g_scalars[1];
    float Kzp = g_scalars[2];

    long long i4 = (long long)(blockIdx.x * blockDim.x + threadIdx.x) * 4;
    if (i4 >= N) return;

    long long NN = N;
    float4 t4  = *(const float4*)(t + i4);
    float4 x14 = *(const float4*)(z + i4);
    float4 v14 = *(const float4*)(z + NN + i4);
    float4 x24 = *(const float4*)(z + 2 * NN + i4);
    float4 v24 = *(const float4*)(z + 3 * NN + i4);
    float4 xc4 = *(const float4*)(z + 4 * NN + i4);

    float4 o0, o1, o2, o3, o4;
    rhs_one(t4.x, x14.x, v14.x, x24.x, v24.x, xc4.x, K, pc, Kzp, o0.x, o1.x, o2.x, o3.x, o4.x);
    rhs_one(t4.y, x14.y, v14.y, x24.y, v24.y, xc4.y, K, pc, Kzp, o0.y, o1.y, o2.y, o3.y, o4.y);
    rhs_one(t4.z, x14.z, v14.z, x24.z, v24.z, xc4.z, K, pc, Kzp, o0.z, o1.z, o2.z, o3.z, o4.z);
    rhs_one(t4.w, x14.w, v14.w, x24.w, v24.w, xc4.w, K, pc, Kzp, o0.w, o1.w, o2.w, o3.w, o4.w);

    *(float4*)(out + i4)          = o0;
    *(float4*)(out + NN + i4)     = o1;
    *(float4*)(out + 2 * NN + i4) = o2;
    *(float4*)(out + 3 * NN + i4) = o3;
    *(float4*)(out + 4 * NN + i4) = o4;
}

// scalar fallback (N % 4 != 0)
__global__ void rhs_kernel_scalar(const float* __restrict__ t,
                                  const float* __restrict__ z,
                                  float* __restrict__ out, int N) {
    float K   = g_scalars[0];
    float pc  = g_scalars[1];
    float Kzp = g_scalars[2];

    long long i = blockIdx.x * blockDim.x + threadIdx.x;
    if (i >= N) return;
    long long NN = N;
    float d0, d1, d2, d3, d4;
    rhs_one(t[i], z[i], z[NN + i], z[2 * NN + i], z[3 * NN + i], z[4 * NN + i],
            K, pc, Kzp, d0, d1, d2, d3, d4);
    out[i]          = d0;
    out[NN + i]     = d1;
    out[2 * NN + i] = d2;
    out[3 * NN + i] = d3;
    out[4 * NN + i] = d4;
}

// ---------------------------------------------------------------------------

extern "C" void kernel_launch(void* const* d_in, const int* in_sizes, int n_in,
                              void* d_out, int out_size) {
    const float* t    = (const float*)d_in[0];
    const float* z    = (const float*)d_in[1];
    const float* logK = (const float*)d_in[2];
    const float* logz = (const float*)d_in[3];
    const float* logp = (const float*)d_in[4];
    const float* W1   = (const float*)d_in[5];
    const float* b1   = (const float*)d_in[6];
    const float* W2   = (const float*)d_in[7];
    const float* b2   = (const float*)d_in[8];
    float* out = (float*)d_out;
    int N = in_sizes[0];

    // one warp per node
    int setup_threads = NNODES * 32;
    setup_nodes<<<(setup_threads + 255) / 256, 256>>>(logK, logz, logp, W1, b1, W2, b2);

    if ((N & 3) == 0) {
        int nthreads = N / 4;
        rhs_kernel_vec<<<(nthreads + 255) / 256, 256>>>(t, z, out, N);
    } else {
        rhs_kernel_scalar<<<(N + 255) / 256, 256>>>(t, z, out, N);
    }
}

// round 7
// speedup vs baseline: 1.6018x; 1.1856x over previous
#include <cuda_runtime.h>
#include <cuda_bf16.h>
#include <math.h>

// ============================================================================
// ControlledSystem RHS (2-mass + controller + Karnopp friction w/ MLP mags).
//
// R6: vec4 + global __ldg packed 8KB table = 11.2us main, 1.4us setup (12.7
// total). Main kernel latency-bound: occ 59% (40 regs -> 6 blocks/SM) and a
// ragged second wave (grid 1024 vs 888 capacity).
// R7: __launch_bounds__(256, 8) forces 32 regs -> 8 blocks/SM (64 warps,
// 100% theoretical occ) AND single-wave execution (capacity 1184 >= 1024).
// Everything else unchanged from the measured-best R6 structure.
// ============================================================================

#define TBL 512
#define NNODES (TBL + 1)
#define VMIN (-8.0f)
#define INV_STEP 32.0f           // TBL / 16.0  (range [-8, 8])
#define STEP (1.0f / 32.0f)

// packed table: g_table[i] = (kin_i, sti_i, kin_{i+1}, sti_{i+1})
__device__ __align__(16) float4 g_table[TBL];
__device__ float g_scalars[4];   // K, p_ctrl, K*(z_ctrl - p_ctrl)

// ---------------------------------------------------------------------------

__device__ __forceinline__ float fast_tanh(float x) {
    return 1.0f - 2.0f / (__expf(2.0f * x) + 1.0f);
}

__device__ __forceinline__ float fast_softplus(float x) {
    if (x > 15.0f) return x;
    return log1pf(__expf(x));
}

// One warp per node; lane handles hidden units (lane) and (lane+32).
// Lane 0 writes the node's (kin, sti) into BOTH packed slots that need it.
__global__ void setup_nodes(const float* __restrict__ logK,
                            const float* __restrict__ logz,
                            const float* __restrict__ logp,
                            const float* __restrict__ W1,
                            const float* __restrict__ b1,
                            const float* __restrict__ W2,
                            const float* __restrict__ b2) {
    int gtid = blockIdx.x * blockDim.x + threadIdx.x;
    int node = gtid >> 5;
    int lane = gtid & 31;

    if (gtid == 0) {
        float K  = expf(logK[0]);
        float zc = expf(logz[0]);
        float pc = expf(logp[0]);
        g_scalars[0] = K;
        g_scalars[1] = pc;
        g_scalars[2] = K * (zc - pc);
    }
    if (node >= NNODES) return;

    float v = VMIN + (float)node * STEP;
    float o0 = 0.0f, o1 = 0.0f;
#pragma unroll
    for (int r = 0; r < 2; ++r) {
        int j = lane + 32 * r;
        float h = fast_tanh(fmaf(v, W1[j], b1[j]));
        o0 = fmaf(h, W2[2 * j + 0], o0);
        o1 = fmaf(h, W2[2 * j + 1], o1);
    }
#pragma unroll
    for (int off = 16; off > 0; off >>= 1) {
        o0 += __shfl_down_sync(0xffffffffu, o0, off);
        o1 += __shfl_down_sync(0xffffffffu, o1, off);
    }
    if (lane == 0) {
        float kin = fast_softplus(o0 + b2[0]);
        float sti = fast_softplus(o1 + b2[1]);
        if (node < TBL) {
            g_table[node].x = kin;
            g_table[node].y = sti;
        }
        if (node > 0) {
            g_table[node - 1].z = kin;
            g_table[node - 1].w = sti;
        }
    }
}

// ---------------------------------------------------------------------------
// Per-element physics. M1=1, M2=1.5, K1=2, K2=3, C1=0.5, C2=0.8, dv=0.01,
// x2_ref = 0.5*sin(0.5*t).
// dv1 = u - 5*x1 - 1.3*v1 + 3*x2 + 0.8*v2   (flattened to FMAs)
// ---------------------------------------------------------------------------

__device__ __forceinline__ void rhs_one(float tt, float x1, float v1, float x2,
                                        float v2, float xc,
                                        float K, float pc, float Kzp,
                                        float& d0, float& d1, float& d2,
                                        float& d3, float& d4) {
    float x2r = 0.5f * __sinf(0.5f * tt);
    float e = x2r - x2;
    d4 = fmaf(-pc, xc, e);                 // d_xc
    float u = fmaf(Kzp, xc, K * e);

    d0 = v1;                               // dx1
    float acc = fmaf(-5.0f, x1, u);
    acc = fmaf(-1.3f, v1, acc);
    acc = fmaf(3.0f, x2, acc);
    d1 = fmaf(0.8f, v2, acc);              // dv1 (M1=1)
    d2 = v2;                               // dx2

    float F = fmaf(3.0f, x1 - x2, 0.8f * (v1 - v2));   // F_net

    // friction magnitudes via packed table (post-softplus, linear interp)
    float vcl = fminf(fmaxf(v2, -8.0f), 8.0f);
    float xi = (vcl + 8.0f) * INV_STEP;
    int idx = (int)xi;
    idx = min(idx, TBL - 1);
    float fr = xi - (float)idx;
    float4 ent = __ldg(&g_table[idx]);
    float kin = fmaf(fr, ent.z - ent.x, ent.x);
    float sti = fmaf(fr, ent.w - ent.y, ent.y);

    float Ff = (fabsf(v2) < 0.01f)
                   ? (-fminf(fmaxf(F, -sti), sti))   // static: -clip(F,+/-sti)
                   : (-copysignf(kin, v2));          // kinetic
    d3 = (F + Ff) * (1.0f / 1.5f);         // dv2 (M2=1.5)
}

// ---------------------------------------------------------------------------
// Main streaming kernel, float4 vectorized (requires N % 4 == 0).
// __launch_bounds__(256, 8): force 32 regs -> 8 blocks/SM, single wave.
// ---------------------------------------------------------------------------

__global__ __launch_bounds__(256, 8) void rhs_kernel_vec(
    const float* __restrict__ t,
    const float* __restrict__ z,
    float* __restrict__ out, int N) {
    float K   = g_scalars[0];
    float pc  = g_scalars[1];
    float Kzp = g_scalars[2];

    long long i4 = (long long)(blockIdx.x * blockDim.x + threadIdx.x) * 4;
    if (i4 >= N) return;

    long long NN = N;
    float4 t4  = *(const float4*)(t + i4);
    float4 x14 = *(const float4*)(z + i4);
    float4 v14 = *(const float4*)(z + NN + i4);
    float4 x24 = *(const float4*)(z + 2 * NN + i4);
    float4 v24 = *(const float4*)(z + 3 * NN + i4);
    float4 xc4 = *(const float4*)(z + 4 * NN + i4);

    float4 o0, o1, o2, o3, o4;
    rhs_one(t4.x, x14.x, v14.x, x24.x, v24.x, xc4.x, K, pc, Kzp, o0.x, o1.x, o2.x, o3.x, o4.x);
    rhs_one(t4.y, x14.y, v14.y, x24.y, v24.y, xc4.y, K, pc, Kzp, o0.y, o1.y, o2.y, o3.y, o4.y);
    rhs_one(t4.z, x14.z, v14.z, x24.z, v24.z, xc4.z, K, pc, Kzp, o0.z, o1.z, o2.z, o3.z, o4.z);
    rhs_one(t4.w, x14.w, v14.w, x24.w, v24.w, xc4.w, K, pc, Kzp, o0.w, o1.w, o2.w, o3.w, o4.w);

    *(float4*)(out + i4)          = o0;
    *(float4*)(out + NN + i4)     = o1;
    *(float4*)(out + 2 * NN + i4) = o2;
    *(float4*)(out + 3 * NN + i4) = o3;
    *(float4*)(out + 4 * NN + i4) = o4;
}

// scalar fallback (N % 4 != 0)
__global__ void rhs_kernel_scalar(const float* __restrict__ t,
                                  const float* __restrict__ z,
                                  float* __restrict__ out, int N) {
    float K   = g_scalars[0];
    float pc  = g_scalars[1];
    float Kzp = g_scalars[2];

    long long i = blockIdx.x * blockDim.x + threadIdx.x;
    if (i >= N) return;
    long long NN = N;
    float d0, d1, d2, d3, d4;
    rhs_one(t[i], z[i], z[NN + i], z[2 * NN + i], z[3 * NN + i], z[4 * NN + i],
            K, pc, Kzp, d0, d1, d2, d3, d4);
    out[i]          = d0;
    out[NN + i]     = d1;
    out[2 * NN + i] = d2;
    out[3 * NN + i] = d3;
    out[4 * NN + i] = d4;
}

// ---------------------------------------------------------------------------

extern "C" void kernel_launch(void* const* d_in, const int* in_sizes, int n_in,
                              void* d_out, int out_size) {
    const float* t    = (const float*)d_in[0];
    const float* z    = (const float*)d_in[1];
    const float* logK = (const float*)d_in[2];
    const float* logz = (const float*)d_in[3];
    const float* logp = (const float*)d_in[4];
    const float* W1   = (const float*)d_in[5];
    const float* b1   = (const float*)d_in[6];
    const float* W2   = (const float*)d_in[7];
    const float* b2   = (const float*)d_in[8];
    float* out = (float*)d_out;
    int N = in_sizes[0];

    // one warp per node
    int setup_threads = NNODES * 32;
    setup_nodes<<<(setup_threads + 255) / 256, 256>>>(logK, logz, logp, W1, b1, W2, b2);

    if ((N & 3) == 0) {
        int nthreads = N / 4;
        rhs_kernel_vec<<<(nthreads + 255) / 256, 256>>>(t, z, out, N);
    } else {
        rhs_kernel_scalar<<<(N + 255) / 256, 256>>>(t, z, out, N);
    }
}